// round 14
// baseline (speedup 1.0000x reference)
#include <cuda_runtime.h>
#include <cuda_fp16.h>
#include <cstdint>

#define BB 128
#define TT 1024
#define HH 256
#define RW 160           // RNN: W_hh columns in registers (measured-best split)
#define SW 96            // RNN: W_hh columns in shared memory
#define NWORK (36 * BB)  // gram work items
#define NPREP (8 * BB)   // prep work items (batch, window)
#define NCTA 148

// scratch
__device__ float g_sq[BB * TT];
__device__ __half g_phi[(size_t)BB * TT * HH];
__device__ __half g_pc [(size_t)BB * TT * HH];
__device__ int g_progress[BB];
__device__ int g_prep_flag[NPREP];
__device__ unsigned g_ticket_prep;
__device__ unsigned g_ticket_gram;

// ======================= helpers =======================
__device__ __forceinline__ uint32_t smem_u32(const void* p) {
    uint32_t a;
    asm("{ .reg .u64 t; cvta.to.shared.u64 t, %1; cvt.u32.u64 %0, t; }" : "=r"(a) : "l"(p));
    return a;
}
__device__ __forceinline__ void ldsm4(uint32_t& r0, uint32_t& r1, uint32_t& r2, uint32_t& r3,
                                      uint32_t addr) {
    asm volatile("ldmatrix.sync.aligned.m8n8.x4.shared.b16 {%0,%1,%2,%3}, [%4];"
                 : "=r"(r0), "=r"(r1), "=r"(r2), "=r"(r3) : "r"(addr));
}
__device__ __forceinline__ void mma16816(float* d, const uint32_t* a, uint32_t b0, uint32_t b1) {
    asm volatile("mma.sync.aligned.m16n8k16.row.col.f32.f16.f16.f32 "
                 "{%0,%1,%2,%3},{%4,%5,%6,%7},{%8,%9},{%0,%1,%2,%3};"
                 : "+f"(d[0]), "+f"(d[1]), "+f"(d[2]), "+f"(d[3])
                 : "r"(a[0]), "r"(a[1]), "r"(a[2]), "r"(a[3]), "r"(b0), "r"(b1));
}
__device__ __forceinline__ unsigned h2u(__half2 v) {
    return *reinterpret_cast<unsigned*>(&v);
}
__device__ __forceinline__ int swz(int off) { return off ^ ((off >> 3) & 0x70); }

__device__ __forceinline__ void cpa16(uint32_t dst, const void* src) {
    asm volatile("cp.async.cg.shared.global [%0], [%1], 16;" :: "r"(dst), "l"(src));
}
#define CP_COMMIT() asm volatile("cp.async.commit_group;" ::: "memory")
#define CP_WAIT(n)  asm volatile("cp.async.wait_group %0;" :: "n"(n) : "memory")

__device__ __forceinline__ int ld_acquire(const int* p) {
    int v;
    asm volatile("ld.acquire.gpu.b32 %0, [%1];" : "=r"(v) : "l"(p) : "memory");
    return v;
}

// ---------------------------------------------------------------------------
// Reset kernel: clears replay-stateful scratch.
// ---------------------------------------------------------------------------
__global__ void reset_kernel()
{
    const int i = threadIdx.x;
    if (i < NPREP) g_prep_flag[i] = 0;
    if (i < BB) g_progress[i] = 0;
    if (i == 0) { g_ticket_prep = 0; g_ticket_gram = 0; }
}

// ---------------------------------------------------------------------------
// Gram SMEM layout: 2 x 64KB tile stages; epilogue stage overlaps buffer 0.
// ---------------------------------------------------------------------------
#define GT_STAGE 65536
#define GT_TILE  16384
#define GT_SMEM  131072

__device__ __forceinline__ void issue_chunk(int b, int tib, int tjb, int kk,
                                            uint32_t sdst, int tid)
{
    const __half* phiA = g_phi + ((size_t)b * TT + tib) * HH;
    const __half* pcA  = g_pc  + ((size_t)b * TT + tib) * HH;
    const __half* phiB = g_phi + ((size_t)b * TT + tjb) * HH;
    const __half* pcB  = g_pc  + ((size_t)b * TT + tjb) * HH;
#pragma unroll
    for (int m = 0; m < 4; ++m) {
        const int g = m * 256 + tid;        // 0..1023 : 128 rows x 8 x 16B
        const int row = g >> 3;
        const int k8 = (g & 7) * 8;
        const int off = swz(row * 128 + k8 * 2);
        const size_t gsrc = (size_t)row * HH + kk + k8;
        cpa16(sdst + 0 * GT_TILE + off, phiA + gsrc);
        cpa16(sdst + 1 * GT_TILE + off, pcA + gsrc);
        cpa16(sdst + 2 * GT_TILE + off, phiB + gsrc);
        cpa16(sdst + 3 * GT_TILE + off, pcB + gsrc);
    }
}

// ---------------------------------------------------------------------------
// Fused persistent kernel.
// CTA 0..127   : RNN for batch blockIdx.x (pristine R12 code + progress
//                publish every 128 steps), then joins the gram pool.
// CTA 128..131 : prep pool (sq + fp16 hi/c split per (batch,window) ticket,
//                release per-window flag), then joins the gram pool.
// CTA 132..147 : gram pool directly (tickets tj-major; acquire-wait on the
//                two window flags each tile needs).
// ---------------------------------------------------------------------------
__global__ void __launch_bounds__(256, 1) fused_kernel(
    const float* __restrict__ x,   const float* __restrict__ W1,
    const float* __restrict__ b1,  const float* __restrict__ W2,
    const float* __restrict__ b2,  const float* __restrict__ Wih,
    const float* __restrict__ Whh, float* __restrict__ p_out,
    float* __restrict__ corr)
{
    extern __shared__ char smc[];
    __shared__ unsigned s_w;
    __shared__ float sqa[128], sqb[128];

    const int tid = threadIdx.x;
    const int wid = tid >> 5;
    const int lane = tid & 31;

    // ================= RNN phase (CTAs 0..127) =================
    if (blockIdx.x < BB) {
        float* sm = reinterpret_cast<float*>(smc);
        float* hbuf = sm;            // 2 * 256 (ping-pong h)
        float* hid  = sm + 512;      // 64
        float* Ws   = sm + 576;      // SW * 256

        const int j = tid;
        const int b = blockIdx.x;

        for (int k = 0; k < SW; ++k)
            Ws[k * HH + j] = Whh[j * HH + RW + k];

        float wr[RW];
#pragma unroll
        for (int k = 0; k < RW; ++k) wr[k] = Whh[j * HH + k];

        const float wi0 = Wih[j * 3 + 0];
        const float wi1 = Wih[j * 3 + 1];
        const float wi2 = Wih[j * 3 + 2];

        if (j < 64) {
            float s = b1[j] + W1[j * 2 + 0] + W1[j * 2 + 1];
            hid[j] = fmaxf(s, 0.f);
        }
        __syncthreads();
        {
            float acc = b2[j];
#pragma unroll
            for (int k = 0; k < 64; ++k) acc = fmaf(W2[j * 64 + k], hid[k], acc);
            hbuf[j] = fmaxf(acc, 0.f);
        }
        __syncthreads();

        const float* xb = x + (size_t)b * TT * 3;
        float* pb = p_out + (size_t)b * TT * HH;

        int cur = 0;
        for (int t = 0; t < TT; ++t) {
            const float x0 = __ldg(xb + t * 3 + 0);
            const float x1 = __ldg(xb + t * 3 + 1);
            const float x2 = __ldg(xb + t * 3 + 2);
            const float* hc = hbuf + cur * HH;

            float a0 = wi0 * x0;
            float a1 = wi1 * x1;
            float a2 = wi2 * x2;
            float a3 = 0.f;

#pragma unroll
            for (int k = 0; k < RW; k += 4) {
                float4 h4 = *reinterpret_cast<const float4*>(hc + k);
                a0 = fmaf(wr[k + 0], h4.x, a0);
                a1 = fmaf(wr[k + 1], h4.y, a1);
                a2 = fmaf(wr[k + 2], h4.z, a2);
                a3 = fmaf(wr[k + 3], h4.w, a3);
            }
#pragma unroll
            for (int k = 0; k < SW; k += 4) {
                float4 h4 = *reinterpret_cast<const float4*>(hc + RW + k);
                a0 = fmaf(Ws[(k + 0) * HH + j], h4.x, a0);
                a1 = fmaf(Ws[(k + 1) * HH + j], h4.y, a1);
                a2 = fmaf(Ws[(k + 2) * HH + j], h4.z, a2);
                a3 = fmaf(Ws[(k + 3) * HH + j], h4.w, a3);
            }

            const float h = fmaxf((a0 + a1) + (a2 + a3), 0.f);
            hbuf[(cur ^ 1) * HH + j] = h;
            pb[(size_t)t * HH + j] = h;
            __syncthreads();
            cur ^= 1;

            if ((t & 127) == 127) {
                __threadfence();
                __syncthreads();
                if (j == 0) atomicExch(&g_progress[b], t + 1);
            }
        }
    }
    // ================= Prep pool (CTAs 128..131) =================
    else if (blockIdx.x < BB + 4) {
        while (true) {
            __syncthreads();
            if (tid == 0) s_w = atomicAdd(&g_ticket_prep, 1u);
            __syncthreads();
            const unsigned pt = s_w;
            if (pt >= NPREP) break;
            const int win = (int)(pt >> 7);       // window-major
            const int b = (int)(pt & 127);

            if (tid == 0) {
                const int need = (win + 1) * 128;
                while (ld_acquire(&g_progress[b]) < need) __nanosleep(200);
            }
            __syncthreads();

            // process 128 rows: warp per row, 16 iterations
            for (int it = 0; it < 16; ++it) {
                const int row = win * 128 + it * 8 + wid;
                const size_t gr = (size_t)b * TT + row;
                const float* pr = p_out + gr * HH;

                float4 v0 = *reinterpret_cast<const float4*>(pr + lane * 4);
                float4 v1 = *reinterpret_cast<const float4*>(pr + 128 + lane * 4);

                float s = v0.x * v0.x + v0.y * v0.y + v0.z * v0.z + v0.w * v0.w
                        + v1.x * v1.x + v1.y * v1.y + v1.z * v1.z + v1.w * v1.w;
#pragma unroll
                for (int o = 16; o > 0; o >>= 1) s += __shfl_xor_sync(0xFFFFFFFFu, s, o);
                if (lane == 0) g_sq[gr] = s;

                __half* phi = g_phi + gr * HH;
                __half* pc  = g_pc  + gr * HH;
#pragma unroll
                for (int half = 0; half < 2; ++half) {
                    const float4 v = half ? v1 : v0;
                    const int col = half * 128 + lane * 4;
                    __half h0 = __float2half(v.x), h1 = __float2half(v.y);
                    __half h2 = __float2half(v.z), h3 = __float2half(v.w);
                    __half c0 = __float2half(fmaf(2.f, v.x - __half2float(h0), __half2float(h0)));
                    __half c1 = __float2half(fmaf(2.f, v.y - __half2float(h1), __half2float(h1)));
                    __half c2 = __float2half(fmaf(2.f, v.z - __half2float(h2), __half2float(h2)));
                    __half c3 = __float2half(fmaf(2.f, v.w - __half2float(h3), __half2float(h3)));
                    uint2 hp = make_uint2(h2u(__halves2half2(h0, h1)), h2u(__halves2half2(h2, h3)));
                    uint2 cp = make_uint2(h2u(__halves2half2(c0, c1)), h2u(__halves2half2(c2, c3)));
                    *reinterpret_cast<uint2*>(phi + col) = hp;
                    *reinterpret_cast<uint2*>(pc + col)  = cp;
                }
            }

            __syncthreads();
            __threadfence();
            __syncthreads();
            if (tid == 0) atomicExch(&g_prep_flag[b * 8 + win], 1);
        }
    }

    // ================= Gram pool (all CTAs) =================
    const uint32_t sbase = smem_u32(smc);
    float* stage = reinterpret_cast<float*>(smc);    // reuse (within-item, after sync)
    const int warp_m = wid >> 2;       // 0..1
    const int warp_n = wid & 3;        // 0..3

    const int a_row = warp_m * 64 + (lane & 7) + ((lane >> 3) & 1) * 8;  // + mt*16
    const int a_k8  = ((lane >> 4) & 1) * 8;                             // + ks*16
    const int b_row = warp_n * 32 + (lane & 7) + ((lane >> 4) & 1) * 8;  // + nt2*16
    const int b_k8  = ((lane >> 3) & 1) * 8;                             // + ks*16

    while (true) {
        __syncthreads();               // protect s_w / stage from previous item
        if (tid == 0) s_w = atomicAdd(&g_ticket_gram, 1u);
        __syncthreads();
        const unsigned w = s_w;
        if (w >= NWORK) break;

        // decode ticket, tj-major (earliest-ready tiles first)
        int tj = 0, base = 0;
        while ((int)w - base >= (tj + 1) * BB) { base += (tj + 1) * BB; ++tj; }
        const int r = (int)w - base;
        const int b = r & 127;
        const int ti = r >> 7;
        const int tib = ti * 128;
        const int tjb = tj * 128;

        if (tid == 0) {
            while (ld_acquire(&g_prep_flag[b * 8 + ti]) == 0) __nanosleep(100);
            while (ld_acquire(&g_prep_flag[b * 8 + tj]) == 0) __nanosleep(100);
        }
        __syncthreads();

        if (tid < 128) sqa[tid] = g_sq[b * TT + tib + tid];
        else           sqb[tid - 128] = g_sq[b * TT + tjb + (tid - 128)];

        float acc[4][4][4];
#pragma unroll
        for (int i = 0; i < 4; ++i)
#pragma unroll
            for (int jj = 0; jj < 4; ++jj)
#pragma unroll
                for (int f = 0; f < 4; ++f) acc[i][jj][f] = 0.f;

        issue_chunk(b, tib, tjb, 0, sbase, tid);
        CP_COMMIT();

#pragma unroll
        for (int chunk = 0; chunk < 4; ++chunk) {
            if (chunk < 3) {
                issue_chunk(b, tib, tjb, (chunk + 1) * 64,
                            sbase + ((chunk + 1) & 1) * GT_STAGE, tid);
                CP_COMMIT();
                CP_WAIT(1);
            } else {
                CP_WAIT(0);
            }
            __syncthreads();

            const uint32_t st = sbase + (chunk & 1) * GT_STAGE;
#pragma unroll
            for (int ks = 0; ks < 4; ++ks) {
                uint32_t bh[8], bc[8];
#pragma unroll
                for (int nt2 = 0; nt2 < 2; ++nt2) {
                    const int off = swz((b_row + nt2 * 16) * 128 + (ks * 16 + b_k8) * 2);
                    ldsm4(bh[nt2 * 4 + 0], bh[nt2 * 4 + 1], bh[nt2 * 4 + 2], bh[nt2 * 4 + 3],
                          st + 2 * GT_TILE + off);
                    ldsm4(bc[nt2 * 4 + 0], bc[nt2 * 4 + 1], bc[nt2 * 4 + 2], bc[nt2 * 4 + 3],
                          st + 3 * GT_TILE + off);
                }
#pragma unroll
                for (int mt = 0; mt < 4; ++mt) {
                    const int off = swz((a_row + mt * 16) * 128 + (ks * 16 + a_k8) * 2);
                    uint32_t ah[4], ac[4];
                    ldsm4(ah[0], ah[1], ah[2], ah[3], st + 0 * GT_TILE + off);
                    ldsm4(ac[0], ac[1], ac[2], ac[3], st + 1 * GT_TILE + off);
#pragma unroll
                    for (int nt = 0; nt < 4; ++nt) {
                        mma16816(acc[mt][nt], ah, bc[nt * 2 + 0], bc[nt * 2 + 1]);
                        mma16816(acc[mt][nt], ac, bh[nt * 2 + 0], bh[nt * 2 + 1]);
                    }
                }
            }
            __syncthreads();
        }

        // epilogue: acc == 2*gram, so dp = s_i + s_j - acc directly
#pragma unroll
        for (int mt = 0; mt < 4; ++mt) {
            const int r0 = warp_m * 64 + mt * 16 + (lane >> 2);
            const int r1 = r0 + 8;
            const float s0 = sqa[r0], s1 = sqa[r1];
#pragma unroll
            for (int nt = 0; nt < 4; ++nt) {
                const int c = warp_n * 32 + nt * 8 + 2 * (lane & 3);
                const float q0 = sqb[c], q1 = sqb[c + 1];
                const float* d = acc[mt][nt];
                stage[r0 * 133 + c]     = __expf(-fmaxf(s0 + q0 - d[0], 0.f));
                stage[r0 * 133 + c + 1] = __expf(-fmaxf(s0 + q1 - d[1], 0.f));
                stage[r1 * 133 + c]     = __expf(-fmaxf(s1 + q0 - d[2], 0.f));
                stage[r1 * 133 + c + 1] = __expf(-fmaxf(s1 + q1 - d[3], 0.f));
            }
        }
        __syncthreads();

        float* cb = corr + (size_t)b * TT * TT;
#pragma unroll
        for (int m = 0; m < 16; ++m) {
            const int idx = m * 256 + tid;
            const int row = idx >> 5;
            const int c4 = (idx & 31) * 4;
            float4 v = make_float4(stage[row * 133 + c4],     stage[row * 133 + c4 + 1],
                                   stage[row * 133 + c4 + 2], stage[row * 133 + c4 + 3]);
            *reinterpret_cast<float4*>(cb + (size_t)(tib + row) * TT + tjb + c4) = v;
        }
        if (ti != tj) {
            for (int m = 0; m < 64; ++m) {
                const int idx = m * 256 + tid;
                const int c = idx >> 7;
                const int rr = idx & 127;
                cb[(size_t)(tjb + c) * TT + tib + rr] = stage[rr * 133 + c];
            }
        }
    }
}

// ---------------------------------------------------------------------------
extern "C" void kernel_launch(void* const* d_in, const int* in_sizes, int n_in,
                              void* d_out, int out_size)
{
    const float* x   = (const float*)d_in[0];
    const float* W1  = (const float*)d_in[1];
    const float* b1  = (const float*)d_in[2];
    const float* W2  = (const float*)d_in[3];
    const float* b2  = (const float*)d_in[4];
    const float* Wih = (const float*)d_in[5];
    const float* Whh = (const float*)d_in[6];

    float* out  = (float*)d_out;
    float* corr = out;                                 // [B, T, T]
    float* p    = out + (size_t)BB * TT * TT;          // [B, T, H]

    cudaFuncSetAttribute(fused_kernel, cudaFuncAttributeMaxDynamicSharedMemorySize, GT_SMEM);

    reset_kernel<<<1, 1024>>>();
    fused_kernel<<<NCTA, 256, GT_SMEM>>>(x, W1, b1, W2, b2, Wih, Whh, p, corr);
}

// round 15
// speedup vs baseline: 2.1605x; 2.1605x over previous
#include <cuda_runtime.h>
#include <cuda_fp16.h>
#include <cstdint>

#define BB 128
#define TT 1024
#define HH 256
#define RW 160           // RNN: W_hh columns in registers (measured-best split)
#define SW 96            // RNN: W_hh columns in shared memory

// scratch: per-row squared norms + fp16 split of p (hi, c = hi + 2*lo)
__device__ float g_sq[BB * TT];
__device__ __half g_phi[(size_t)BB * TT * HH];
__device__ __half g_pc [(size_t)BB * TT * HH];

// ======================= warp-MMA helpers (base-PTX, sm_80+) ================
__device__ __forceinline__ uint32_t smem_u32(const void* p) {
    uint32_t a;
    asm("{ .reg .u64 t; cvta.to.shared.u64 t, %1; cvt.u32.u64 %0, t; }" : "=r"(a) : "l"(p));
    return a;
}
__device__ __forceinline__ void ldsm4(uint32_t& r0, uint32_t& r1, uint32_t& r2, uint32_t& r3,
                                      uint32_t addr) {
    asm volatile("ldmatrix.sync.aligned.m8n8.x4.shared.b16 {%0,%1,%2,%3}, [%4];"
                 : "=r"(r0), "=r"(r1), "=r"(r2), "=r"(r3) : "r"(addr));
}
__device__ __forceinline__ void mma16816(float* d, const uint32_t* a, uint32_t b0, uint32_t b1) {
    asm volatile("mma.sync.aligned.m16n8k16.row.col.f32.f16.f16.f32 "
                 "{%0,%1,%2,%3},{%4,%5,%6,%7},{%8,%9},{%0,%1,%2,%3};"
                 : "+f"(d[0]), "+f"(d[1]), "+f"(d[2]), "+f"(d[3])
                 : "r"(a[0]), "r"(a[1]), "r"(a[2]), "r"(a[3]), "r"(b0), "r"(b1));
}
__device__ __forceinline__ unsigned h2u(__half2 v) {
    return *reinterpret_cast<unsigned*>(&v);
}
__device__ __forceinline__ int swz(int off) { return off ^ ((off >> 3) & 0x70); }

__device__ __forceinline__ void cpa16(uint32_t dst, const void* src) {
    asm volatile("cp.async.cg.shared.global [%0], [%1], 16;" :: "r"(dst), "l"(src));
}
#define CP_COMMIT() asm volatile("cp.async.commit_group;" ::: "memory")
#define CP_WAIT(n)  asm volatile("cp.async.wait_group %0;" :: "n"(n) : "memory")

// ---------------------------------------------------------------------------
// RNN kernel (scalar, measured best): one block per batch, thread j = neuron j
// ---------------------------------------------------------------------------
__global__ void __launch_bounds__(256, 1) rnn_kernel(
    const float* __restrict__ x,   const float* __restrict__ W1,
    const float* __restrict__ b1,  const float* __restrict__ W2,
    const float* __restrict__ b2,  const float* __restrict__ Wih,
    const float* __restrict__ Whh, float* __restrict__ p_out)
{
    extern __shared__ float sm[];
    float* hbuf = sm;            // 2 * 256 (ping-pong h)
    float* hid  = sm + 512;      // 64
    float* Ws   = sm + 576;      // SW * 256

    const int j = threadIdx.x;
    const int b = blockIdx.x;

    for (int k = 0; k < SW; ++k)
        Ws[k * HH + j] = Whh[j * HH + RW + k];

    float wr[RW];
#pragma unroll
    for (int k = 0; k < RW; ++k) wr[k] = Whh[j * HH + k];

    const float wi0 = Wih[j * 3 + 0];
    const float wi1 = Wih[j * 3 + 1];
    const float wi2 = Wih[j * 3 + 2];

    if (j < 64) {
        float s = b1[j] + W1[j * 2 + 0] + W1[j * 2 + 1];
        hid[j] = fmaxf(s, 0.f);
    }
    __syncthreads();
    {
        float acc = b2[j];
#pragma unroll
        for (int k = 0; k < 64; ++k) acc = fmaf(W2[j * 64 + k], hid[k], acc);
        hbuf[j] = fmaxf(acc, 0.f);
    }
    __syncthreads();

    const float* xb = x + (size_t)b * TT * 3;
    float* pb = p_out + (size_t)b * TT * HH;

    int cur = 0;
    for (int t = 0; t < TT; ++t) {
        const float x0 = __ldg(xb + t * 3 + 0);
        const float x1 = __ldg(xb + t * 3 + 1);
        const float x2 = __ldg(xb + t * 3 + 2);
        const float* hc = hbuf + cur * HH;

        float a0 = wi0 * x0;
        float a1 = wi1 * x1;
        float a2 = wi2 * x2;
        float a3 = 0.f;

#pragma unroll
        for (int k = 0; k < RW; k += 4) {
            float4 h4 = *reinterpret_cast<const float4*>(hc + k);
            a0 = fmaf(wr[k + 0], h4.x, a0);
            a1 = fmaf(wr[k + 1], h4.y, a1);
            a2 = fmaf(wr[k + 2], h4.z, a2);
            a3 = fmaf(wr[k + 3], h4.w, a3);
        }
#pragma unroll
        for (int k = 0; k < SW; k += 4) {
            float4 h4 = *reinterpret_cast<const float4*>(hc + RW + k);
            a0 = fmaf(Ws[(k + 0) * HH + j], h4.x, a0);
            a1 = fmaf(Ws[(k + 1) * HH + j], h4.y, a1);
            a2 = fmaf(Ws[(k + 2) * HH + j], h4.z, a2);
            a3 = fmaf(Ws[(k + 3) * HH + j], h4.w, a3);
        }

        const float h = fmaxf((a0 + a1) + (a2 + a3), 0.f);
        hbuf[(cur ^ 1) * HH + j] = h;
        pb[(size_t)t * HH + j] = h;
        __syncthreads();
        cur ^= 1;
    }
}

// ---------------------------------------------------------------------------
// Prep kernel: per-row squared norm + fp16 split of p (hi, c = hi + 2*lo).
// ---------------------------------------------------------------------------
__global__ void prep_kernel(const float* __restrict__ p)
{
    const int w = threadIdx.x >> 5;
    const int lane = threadIdx.x & 31;
    const int row = blockIdx.x * 8 + w;
    const float* pr = p + (size_t)row * HH;

    float4 v0 = *reinterpret_cast<const float4*>(pr + lane * 4);
    float4 v1 = *reinterpret_cast<const float4*>(pr + 128 + lane * 4);

    float s = v0.x * v0.x + v0.y * v0.y + v0.z * v0.z + v0.w * v0.w
            + v1.x * v1.x + v1.y * v1.y + v1.z * v1.z + v1.w * v1.w;
#pragma unroll
    for (int o = 16; o > 0; o >>= 1) s += __shfl_xor_sync(0xFFFFFFFFu, s, o);
    if (lane == 0) g_sq[row] = s;

    __half* phi = g_phi + (size_t)row * HH;
    __half* pc  = g_pc  + (size_t)row * HH;
#pragma unroll
    for (int half = 0; half < 2; ++half) {
        const float4 v = half ? v1 : v0;
        const int col = half * 128 + lane * 4;
        __half h0 = __float2half(v.x), h1 = __float2half(v.y);
        __half h2 = __float2half(v.z), h3 = __float2half(v.w);
        __half c0 = __float2half(fmaf(2.f, v.x - __half2float(h0), __half2float(h0)));
        __half c1 = __float2half(fmaf(2.f, v.y - __half2float(h1), __half2float(h1)));
        __half c2 = __float2half(fmaf(2.f, v.z - __half2float(h2), __half2float(h2)));
        __half c3 = __float2half(fmaf(2.f, v.w - __half2float(h3), __half2float(h3)));
        uint2 hp = make_uint2(h2u(__halves2half2(h0, h1)), h2u(__halves2half2(h2, h3)));
        uint2 cp = make_uint2(h2u(__halves2half2(c0, c1)), h2u(__halves2half2(c2, c3)));
        *reinterpret_cast<uint2*>(phi + col) = hp;
        *reinterpret_cast<uint2*>(pc + col)  = cp;
    }
}

// ---------------------------------------------------------------------------
// Tensor-core gram kernel (mma.sync fp16 c-trick, 2 MMA terms), cp.async
// double-buffered. Inner loop reordered so MMAs sharing an accumulator are
// >= 4 issues apart (breaks the HMMA accumulator-RAW stall chain).
// ---------------------------------------------------------------------------
#define GT_STAGE 65536
#define GT_TILE  16384
#define GT_SMEM  131072

__device__ __forceinline__ void issue_chunk(
    const __half* __restrict__ phiA, const __half* __restrict__ pcA,
    const __half* __restrict__ phiB, const __half* __restrict__ pcB,
    int kk, uint32_t sdst, int tid)
{
#pragma unroll
    for (int m = 0; m < 4; ++m) {
        const int g = m * 256 + tid;        // 0..1023 : 128 rows x 8 x 16B
        const int row = g >> 3;
        const int k8 = (g & 7) * 8;
        const int off = swz(row * 128 + k8 * 2);
        const size_t gsrc = (size_t)row * HH + kk + k8;
        cpa16(sdst + 0 * GT_TILE + off, phiA + gsrc);
        cpa16(sdst + 1 * GT_TILE + off, pcA + gsrc);
        cpa16(sdst + 2 * GT_TILE + off, phiB + gsrc);
        cpa16(sdst + 3 * GT_TILE + off, pcB + gsrc);
    }
}

__global__ void __launch_bounds__(256, 1) gram_mma_kernel(float* __restrict__ corr)
{
    extern __shared__ char smc[];
    float* stage = reinterpret_cast<float*>(smc);    // reused after mainloop
    __shared__ float sqa[128], sqb[128];

    const uint32_t sbase = smem_u32(smc);
    const int tid = threadIdx.x;
    const int wid = tid >> 5;
    const int lane = tid & 31;
    const int warp_m = wid >> 2;       // 0..1
    const int warp_n = wid & 3;        // 0..3

    const int b = blockIdx.y;
    int pair = blockIdx.x;
    int ti = 0;
    while (pair >= 8 - ti) { pair -= (8 - ti); ++ti; }
    const int tj = ti + pair;
    const int tib = ti * 128;
    const int tjb = tj * 128;

    if (tid < 128) sqa[tid] = g_sq[b * TT + tib + tid];
    else           sqb[tid - 128] = g_sq[b * TT + tjb + (tid - 128)];

    const __half* phiA = g_phi + ((size_t)b * TT + tib) * HH;
    const __half* pcA  = g_pc  + ((size_t)b * TT + tib) * HH;
    const __half* phiB = g_phi + ((size_t)b * TT + tjb) * HH;
    const __half* pcB  = g_pc  + ((size_t)b * TT + tjb) * HH;

    const int a_row = warp_m * 64 + (lane & 7) + ((lane >> 3) & 1) * 8;  // + mt*16
    const int a_k8  = ((lane >> 4) & 1) * 8;                             // + ks*16
    const int b_row = warp_n * 32 + (lane & 7) + ((lane >> 4) & 1) * 8;  // + nt2*16
    const int b_k8  = ((lane >> 3) & 1) * 8;                             // + ks*16

    float acc[4][4][4];
#pragma unroll
    for (int i = 0; i < 4; ++i)
#pragma unroll
        for (int jj = 0; jj < 4; ++jj)
#pragma unroll
            for (int f = 0; f < 4; ++f) acc[i][jj][f] = 0.f;

    issue_chunk(phiA, pcA, phiB, pcB, 0, sbase, tid);
    CP_COMMIT();

#pragma unroll
    for (int chunk = 0; chunk < 4; ++chunk) {
        if (chunk < 3) {
            issue_chunk(phiA, pcA, phiB, pcB, (chunk + 1) * 64,
                        sbase + ((chunk + 1) & 1) * GT_STAGE, tid);
            CP_COMMIT();
            CP_WAIT(1);
        } else {
            CP_WAIT(0);
        }
        __syncthreads();

        const uint32_t st = sbase + (chunk & 1) * GT_STAGE;
#pragma unroll
        for (int ks = 0; ks < 4; ++ks) {
            uint32_t bh[8], bc[8];
#pragma unroll
            for (int nt2 = 0; nt2 < 2; ++nt2) {
                const int off = swz((b_row + nt2 * 16) * 128 + (ks * 16 + b_k8) * 2);
                ldsm4(bh[nt2 * 4 + 0], bh[nt2 * 4 + 1], bh[nt2 * 4 + 2], bh[nt2 * 4 + 3],
                      st + 2 * GT_TILE + off);
                ldsm4(bc[nt2 * 4 + 0], bc[nt2 * 4 + 1], bc[nt2 * 4 + 2], bc[nt2 * 4 + 3],
                      st + 3 * GT_TILE + off);
            }
#pragma unroll
            for (int mt = 0; mt < 4; ++mt) {
                const int off = swz((a_row + mt * 16) * 128 + (ks * 16 + a_k8) * 2);
                uint32_t ah[4], ac[4];
                ldsm4(ah[0], ah[1], ah[2], ah[3], st + 0 * GT_TILE + off);
                ldsm4(ac[0], ac[1], ac[2], ac[3], st + 1 * GT_TILE + off);
                // term 1: 4 independent accumulators ...
#pragma unroll
                for (int nt = 0; nt < 4; ++nt)
                    mma16816(acc[mt][nt], ah, bc[nt * 2 + 0], bc[nt * 2 + 1]);
                // ... then term 2: dependent pair is now 4 issues away
#pragma unroll
                for (int nt = 0; nt < 4; ++nt)
                    mma16816(acc[mt][nt], ac, bh[nt * 2 + 0], bh[nt * 2 + 1]);
            }
        }
        __syncthreads();
    }

    // epilogue: acc == 2*gram, so dp = s_i + s_j - acc directly
#pragma unroll
    for (int mt = 0; mt < 4; ++mt) {
        const int r0 = warp_m * 64 + mt * 16 + (lane >> 2);
        const int r1 = r0 + 8;
        const float s0 = sqa[r0], s1 = sqa[r1];
#pragma unroll
        for (int nt = 0; nt < 4; ++nt) {
            const int c = warp_n * 32 + nt * 8 + 2 * (lane & 3);
            const float q0 = sqb[c], q1 = sqb[c + 1];
            const float* d = acc[mt][nt];
            stage[r0 * 133 + c]     = __expf(-fmaxf(s0 + q0 - d[0], 0.f));
            stage[r0 * 133 + c + 1] = __expf(-fmaxf(s0 + q1 - d[1], 0.f));
            stage[r1 * 133 + c]     = __expf(-fmaxf(s1 + q0 - d[2], 0.f));
            stage[r1 * 133 + c + 1] = __expf(-fmaxf(s1 + q1 - d[3], 0.f));
        }
    }
    __syncthreads();

    float* cb = corr + (size_t)b * TT * TT;
#pragma unroll
    for (int m = 0; m < 16; ++m) {
        const int idx = m * 256 + tid;
        const int row = idx >> 5;
        const int c4 = (idx & 31) * 4;
        float4 v = make_float4(stage[row * 133 + c4],     stage[row * 133 + c4 + 1],
                               stage[row * 133 + c4 + 2], stage[row * 133 + c4 + 3]);
        *reinterpret_cast<float4*>(cb + (size_t)(tib + row) * TT + tjb + c4) = v;
    }
    if (ti != tj) {
        for (int m = 0; m < 64; ++m) {
            const int idx = m * 256 + tid;
            const int c = idx >> 7;
            const int r = idx & 127;
            cb[(size_t)(tjb + c) * TT + tib + r] = stage[r * 133 + c];
        }
    }
}

// ---------------------------------------------------------------------------
extern "C" void kernel_launch(void* const* d_in, const int* in_sizes, int n_in,
                              void* d_out, int out_size)
{
    const float* x   = (const float*)d_in[0];
    const float* W1  = (const float*)d_in[1];
    const float* b1  = (const float*)d_in[2];
    const float* W2  = (const float*)d_in[3];
    const float* b2  = (const float*)d_in[4];
    const float* Wih = (const float*)d_in[5];
    const float* Whh = (const float*)d_in[6];

    float* out  = (float*)d_out;
    float* corr = out;                                 // [B, T, T]
    float* p    = out + (size_t)BB * TT * TT;          // [B, T, H]

    const size_t rnn_smem = (size_t)(576 + SW * HH) * sizeof(float);   // ~98.3 KB
    cudaFuncSetAttribute(rnn_kernel,      cudaFuncAttributeMaxDynamicSharedMemorySize, (int)rnn_smem);
    cudaFuncSetAttribute(gram_mma_kernel, cudaFuncAttributeMaxDynamicSharedMemorySize, GT_SMEM);

    rnn_kernel<<<BB, 256, rnn_smem>>>(x, W1, b1, W2, b2, Wih, Whh, p);
    prep_kernel<<<(BB * TT) / 8, 256>>>(p);
    gram_mma_kernel<<<dim3(36, BB), 256, GT_SMEM>>>(corr);
}